// round 7
// baseline (speedup 1.0000x reference)
#include <cuda_runtime.h>
#include <cuda_bf16.h>
#include <cstdint>

typedef unsigned long long ull;

#define E_DIM 128
#define NPG   32
#define TPB   256
#define PAD   132           // fp32 row stride (floats)
#define XSB   272           // bf16 A-tile row stride (bytes)
#define XH32  8704          // bytes per 32-row bf16 tile (32*272)
#define WSB   144           // bf16 W-half row stride (bytes)
#define WHT   18432         // bytes per W half tile (128*144)
#define GWHALF 34816        // g_wconv: bytes per 128-row full-K tile (128*272)
#define WB    69632         // g_wconv: bytes per weight (hi+lo)

// smem byte offsets
#define OFF_W    0          // 36864: W K-half hi/lo (streamed)
#define OFF_X    36864      // 17408: X hi/lo tiles; later V_s fp32 (16896)
#define OFF_C    54272      // 17408: Q_s fp32 (16896); later attn-out hi/lo tiles
#define OFF_D    71680      // 16896: K_s fp32
#define OFF_BIAS 88576      // 512 floats
#define SMEM_TOTAL 90624

__device__ __align__(1024) unsigned char g_wconv[4 * WB];

// ---------- helpers ----------
__device__ __forceinline__ uint32_t s2u(const void* p) {
    uint32_t a;
    asm("{ .reg .u64 t; cvta.to.shared.u64 t, %1; cvt.u32.u64 %0, t; }" : "=r"(a) : "l"(p));
    return a;
}
__device__ __forceinline__ ull pack2(float lo, float hi) {
    ull r; asm("mov.b64 %0, {%1, %2};" : "=l"(r) : "f"(lo), "f"(hi)); return r;
}
__device__ __forceinline__ void unpack2(ull p, float& lo, float& hi) {
    asm("mov.b64 {%0, %1}, %2;" : "=f"(lo), "=f"(hi) : "l"(p));
}
__device__ __forceinline__ void ffma2(ull& d, ull a, ull b) {
    asm("fma.rn.f32x2 %0, %1, %2, %0;" : "+l"(d) : "l"(a), "l"(b));
}
__device__ __forceinline__ ull pack4bf(__nv_bfloat16 a, __nv_bfloat16 b,
                                       __nv_bfloat16 c, __nv_bfloat16 d) {
    uint32_t lo = ((uint32_t)__bfloat16_as_ushort(b) << 16) | __bfloat16_as_ushort(a);
    uint32_t hi = ((uint32_t)__bfloat16_as_ushort(d) << 16) | __bfloat16_as_ushort(c);
    return ((ull)hi << 32) | lo;
}
__device__ __forceinline__ void split4(float4 x, ull& hiw, ull& low) {
    __nv_bfloat16 h0 = __float2bfloat16(x.x), h1 = __float2bfloat16(x.y),
                  h2 = __float2bfloat16(x.z), h3 = __float2bfloat16(x.w);
    __nv_bfloat16 l0 = __float2bfloat16(x.x - __bfloat162float(h0));
    __nv_bfloat16 l1 = __float2bfloat16(x.y - __bfloat162float(h1));
    __nv_bfloat16 l2 = __float2bfloat16(x.z - __bfloat162float(h2));
    __nv_bfloat16 l3 = __float2bfloat16(x.w - __bfloat162float(h3));
    hiw = pack4bf(h0, h1, h2, h3);
    low = pack4bf(l0, l1, l2, l3);
}
__device__ __forceinline__ void ldsm4(uint32_t& r0, uint32_t& r1, uint32_t& r2,
                                      uint32_t& r3, uint32_t a) {
    asm volatile("ldmatrix.sync.aligned.m8n8.x4.shared.b16 {%0,%1,%2,%3}, [%4];"
                 : "=r"(r0), "=r"(r1), "=r"(r2), "=r"(r3) : "r"(a));
}
__device__ __forceinline__ void mma_bf16(float* c, const uint32_t* a,
                                         uint32_t b0, uint32_t b1) {
    asm volatile(
        "mma.sync.aligned.m16n8k16.row.col.f32.bf16.bf16.f32 "
        "{%0,%1,%2,%3}, {%4,%5,%6,%7}, {%8,%9}, {%0,%1,%2,%3};"
        : "+f"(c[0]), "+f"(c[1]), "+f"(c[2]), "+f"(c[3])
        : "r"(a[0]), "r"(a[1]), "r"(a[2]), "r"(a[3]), "r"(b0), "r"(b1));
}
__device__ __forceinline__ void cp16(uint32_t smem, const void* g) {
    asm volatile("cp.async.ca.shared.global [%0], [%1], 16;" :: "r"(smem), "l"(g) : "memory");
}
#define CP_COMMIT() asm volatile("cp.async.commit_group;" ::: "memory")
#define CP_WAIT0()  asm volatile("cp.async.wait_group 0;" ::: "memory")

// ---------- building blocks ----------
// X (32x128 f32, gmem) -> hi/lo bf16 tiles at OFF_X
__device__ __forceinline__ void convert_X(const float* __restrict__ gx, char* raw, int tid) {
    const int row  = tid >> 3;           // 0..31
    const int colb = (tid & 7) * 16;
#pragma unroll
    for (int i = 0; i < 4; i++) {
        const int col = colb + i * 4;
        float4 x = *reinterpret_cast<const float4*>(gx + row * E_DIM + col);
        ull hw, lw; split4(x, hw, lw);
        *(ull*)(raw + OFF_X + row * XSB + col * 2)        = hw;
        *(ull*)(raw + OFF_X + XH32 + row * XSB + col * 2) = lw;
    }
}
// async copy of one K-half of weight wsel: 2048 x 16B chunks
__device__ __forceinline__ void copy_Whalf_async(int wsel, int half, uint32_t sb, int tid) {
    const char* src = reinterpret_cast<const char*>(g_wconv) + wsel * WB + half * 128;
#pragma unroll
    for (int i = 0; i < 8; i++) {
        const int idx = i * TPB + tid;        // 0..2047
        const int hl  = idx >> 10;            // 0=hi, 1=lo
        const int r   = (idx >> 3) & 127;     // W row (output col)
        const int j   = idx & 7;              // 16B chunk within half-row
        cp16(sb + OFF_W + hl * WHT + r * WSB + j * 16,
             src + (size_t)hl * GWHALF + (size_t)r * XSB + j * 16);
    }
    CP_COMMIT();
}

// 4 k8 steps of the 3-split bf16 MMA for one K-half (acc persists across halves)
__device__ __forceinline__ void gemm_half(char* raw, int offA, float acc[4][4],
                                          int w, int l, int half) {
    const int wm = w >> 2, wn = w & 3;       // wm 0..1 (16 rows), wn 0..3 (32 cols)
    const uint32_t sb = s2u(raw);
    const uint32_t aBase = sb + offA + (wm * 16 + (l & 15)) * XSB + (l >> 4) * 16
                         + half * 128;       // +64 k elems = 128B
    const uint32_t bBase = sb + OFF_W +
        (wn * 32 + (l & 7) + ((l >> 4) & 1) * 8) * WSB + ((l >> 3) & 1) * 16;
#pragma unroll
    for (int k8 = 0; k8 < 4; k8++) {
        uint32_t ah[4], al[4];
        ldsm4(ah[0], ah[1], ah[2], ah[3], aBase + k8 * 32);
        ldsm4(al[0], al[1], al[2], al[3], aBase + XH32 + k8 * 32);
        uint32_t bh[8], bl[8];
        ldsm4(bh[0], bh[1], bh[2], bh[3], bBase + k8 * 32);              // subs 0,1
        ldsm4(bh[4], bh[5], bh[6], bh[7], bBase + 16 * WSB + k8 * 32);   // subs 2,3
        ldsm4(bl[0], bl[1], bl[2], bl[3], bBase + WHT + k8 * 32);
        ldsm4(bl[4], bl[5], bl[6], bl[7], bBase + WHT + 16 * WSB + k8 * 32);
#pragma unroll
        for (int sub = 0; sub < 4; sub++) {
            mma_bf16(acc[sub], ah, bh[2 * sub], bh[2 * sub + 1]);  // hi*hi
            mma_bf16(acc[sub], ah, bl[2 * sub], bl[2 * sub + 1]);  // hi*lo
            mma_bf16(acc[sub], al, bh[2 * sub], bh[2 * sub + 1]);  // lo*hi
        }
    }
}
__device__ __forceinline__ void epilogue(const float acc[4][4], const float* bias,
                                         float scale, float* dst, int dstride,
                                         int w, int l) {
    const int wm = w >> 2, wn = w & 3;
    const int r0 = wm * 16 + (l >> 2);
#pragma unroll
    for (int sub = 0; sub < 4; sub++) {
        const int cb = wn * 32 + sub * 8 + (l & 3) * 2;
        float2 v;
        v.x = (acc[sub][0] + bias[cb]) * scale;
        v.y = (acc[sub][1] + bias[cb + 1]) * scale;
        *reinterpret_cast<float2*>(dst + r0 * dstride + cb) = v;
        v.x = (acc[sub][2] + bias[cb]) * scale;
        v.y = (acc[sub][3] + bias[cb + 1]) * scale;
        *reinterpret_cast<float2*>(dst + (r0 + 8) * dstride + cb) = v;
    }
}

// ---------- pre-kernel: weights f32 -> bf16 hi/lo tiles in g_wconv ----------
extern "C" __global__ void wconv_kernel(const float* __restrict__ wq,
                                        const float* __restrict__ wk,
                                        const float* __restrict__ wv,
                                        const float* __restrict__ wo) {
    const int idx = (blockIdx.x * blockDim.x + threadIdx.x) * 4;
    const int wsel = idx >> 14;
    const float* W = (wsel == 0) ? wq : (wsel == 1) ? wk : (wsel == 2) ? wv : wo;
    const int rem = idx & 16383;
    const int c = rem >> 7, k = rem & 127;
    float4 x = *reinterpret_cast<const float4*>(W + c * 128 + k);
    ull hw, lw; split4(x, hw, lw);
    *(ull*)(g_wconv + wsel * WB + c * XSB + k * 2)          = hw;
    *(ull*)(g_wconv + wsel * WB + GWHALF + c * XSB + k * 2) = lw;
}

// ---------- main fused kernel: 1 graph per CTA ----------
extern "C" __global__ void __launch_bounds__(TPB, 2)
iattn_mma3_kernel(const float* __restrict__ query, const float* __restrict__ key,
                  const float* __restrict__ value,
                  const float* __restrict__ bq, const float* __restrict__ bk,
                  const float* __restrict__ bv, const float* __restrict__ bo,
                  float* __restrict__ out)
{
    extern __shared__ char raw[];
    const int tid = threadIdx.x;
    const int w = tid >> 5, l = tid & 31;
    const size_t base = (size_t)blockIdx.x * NPG * E_DIM;
    const uint32_t sb = s2u(raw);
    float* bias_s = reinterpret_cast<float*>(raw + OFF_BIAS);

    copy_Whalf_async(0, 0, sb, tid);       // Wq half0 overlaps bias + convert
    {
        const float* b0 = (tid < 128) ? bq : bk;
        bias_s[tid] = b0[tid & 127];
        const float* b1 = (tid < 128) ? bv : bo;
        bias_s[tid + 256] = b1[tid & 127];
    }

    float acc[4][4];
    const float* gx[3] = {query + base, key + base, value + base};
    const int   offD[3] = {OFF_C, OFF_D, OFF_X};
    const float scl[3]  = {0.25f, 1.0f, 1.0f};

    // --- projection phases ---
#pragma unroll
    for (int ph = 0; ph < 3; ph++) {
#pragma unroll
        for (int s = 0; s < 4; s++)
#pragma unroll
            for (int i = 0; i < 4; i++) acc[s][i] = 0.f;
        convert_X(gx[ph], raw, tid);
        CP_WAIT0();
        __syncthreads();                       // X + W-half0 visible
        gemm_half(raw, OFF_X, acc, w, l, 0);
        __syncthreads();                       // half0 reads done
        copy_Whalf_async(ph, 1, sb, tid);
        CP_WAIT0();
        __syncthreads();
        gemm_half(raw, OFF_X, acc, w, l, 1);
        __syncthreads();                       // A/W reads done (V overlays X next;
                                               // next phase overwrites X/W anyway)
        epilogue(acc, bias_s + ph * 128, scl[ph],
                 reinterpret_cast<float*>(raw + offD[ph]), PAD, w, l);
        if (ph < 2) copy_Whalf_async(ph + 1, 0, sb, tid);  // next W half0
    }
    copy_Whalf_async(3, 0, sb, tid);           // Wo half0 during attention
    __syncthreads();                           // Q_s/K_s/V_s visible

    // --- attention: warp = head h, lane = query row ---
    {
        const float* Qs = reinterpret_cast<const float*>(raw + OFF_C);
        const float* Ks = reinterpret_cast<const float*>(raw + OFF_D);
        const float* Vs = reinterpret_cast<const float*>(raw + OFF_X);
        const int c0 = w * 16;
        const float* qr = Qs + l * PAD + c0;
        ulonglong2 qa = *reinterpret_cast<const ulonglong2*>(qr);
        ulonglong2 qb = *reinterpret_cast<const ulonglong2*>(qr + 4);
        ulonglong2 qc = *reinterpret_cast<const ulonglong2*>(qr + 8);
        ulonglong2 qd = *reinterpret_cast<const ulonglong2*>(qr + 12);

        float sc[NPG];
        float mx = -1e30f;
#pragma unroll
        for (int j = 0; j < NPG; j++) {
            const float* kr = Ks + j * PAD + c0;
            ulonglong2 ka = *reinterpret_cast<const ulonglong2*>(kr);
            ulonglong2 kb = *reinterpret_cast<const ulonglong2*>(kr + 4);
            ulonglong2 kc = *reinterpret_cast<const ulonglong2*>(kr + 8);
            ulonglong2 kd = *reinterpret_cast<const ulonglong2*>(kr + 12);
            ull t2 = 0ULL;
            ffma2(t2, qa.x, ka.x); ffma2(t2, qa.y, ka.y);
            ffma2(t2, qb.x, kb.x); ffma2(t2, qb.y, kb.y);
            ffma2(t2, qc.x, kc.x); ffma2(t2, qc.y, kc.y);
            ffma2(t2, qd.x, kd.x); ffma2(t2, qd.y, kd.y);
            float tl, th; unpack2(t2, tl, th);
            const float t = tl + th;
            sc[j] = t;
            mx = fmaxf(mx, t);
        }
        float sum = 0.f;
#pragma unroll
        for (int j = 0; j < NPG; j++) { sc[j] = __expf(sc[j] - mx); sum += sc[j]; }
        const float inv = 1.0f / sum;

        __syncthreads();   // all warps done reading Q_s before overlaying OFF_C

        ull o2[8];
#pragma unroll
        for (int i = 0; i < 8; i++) o2[i] = 0ULL;
#pragma unroll
        for (int j = 0; j < NPG; j++) {
            const ull p2 = pack2(sc[j], sc[j]);
            const float* vr = Vs + j * PAD + c0;
            ulonglong2 va = *reinterpret_cast<const ulonglong2*>(vr);
            ulonglong2 vb = *reinterpret_cast<const ulonglong2*>(vr + 4);
            ulonglong2 vc = *reinterpret_cast<const ulonglong2*>(vr + 8);
            ulonglong2 vd = *reinterpret_cast<const ulonglong2*>(vr + 12);
            ffma2(o2[0], p2, va.x); ffma2(o2[1], p2, va.y);
            ffma2(o2[2], p2, vb.x); ffma2(o2[3], p2, vb.y);
            ffma2(o2[4], p2, vc.x); ffma2(o2[5], p2, vc.y);
            ffma2(o2[6], p2, vd.x); ffma2(o2[7], p2, vd.y);
        }
        // write attention output as bf16 hi/lo tiles into OFF_C
#pragma unroll
        for (int p = 0; p < 4; p++) {
            float x0, x1, x2, x3;
            unpack2(o2[2 * p],     x0, x1);
            unpack2(o2[2 * p + 1], x2, x3);
            float4 x = make_float4(x0 * inv, x1 * inv, x2 * inv, x3 * inv);
            ull hw, lw; split4(x, hw, lw);
            const int col = c0 + 4 * p;
            *(ull*)(raw + OFF_C + l * XSB + col * 2)        = hw;
            *(ull*)(raw + OFF_C + XH32 + l * XSB + col * 2) = lw;
        }
    }
    CP_WAIT0();
    __syncthreads();   // attn-out tiles + Wo half0 visible

    // --- out projection -> gmem ---
#pragma unroll
    for (int s = 0; s < 4; s++)
#pragma unroll
        for (int i = 0; i < 4; i++) acc[s][i] = 0.f;
    gemm_half(raw, OFF_C, acc, w, l, 0);
    __syncthreads();
    copy_Whalf_async(3, 1, sb, tid);
    CP_WAIT0();
    __syncthreads();
    gemm_half(raw, OFF_C, acc, w, l, 1);
    epilogue(acc, bias_s + 384, 1.0f, out + base, E_DIM, w, l);
}

extern "C" void kernel_launch(void* const* d_in, const int* in_sizes, int n_in,
                              void* d_out, int out_size)
{
    const float* query = (const float*)d_in[0];
    const float* key_  = (const float*)d_in[1];
    const float* value = (const float*)d_in[2];
    const float* wq    = (const float*)d_in[3];
    const float* wk    = (const float*)d_in[4];
    const float* wv    = (const float*)d_in[5];
    const float* bq    = (const float*)d_in[6];
    const float* bk    = (const float*)d_in[7];
    const float* bv    = (const float*)d_in[8];
    const float* wo    = (const float*)d_in[9];
    const float* bo    = (const float*)d_in[10];
    float* out = (float*)d_out;

    const int N = in_sizes[0] / E_DIM;   // total nodes
    const int grid = N / NPG;            // 1 graph per CTA

    wconv_kernel<<<64, 256>>>(wq, wk, wv, wo);

    cudaFuncSetAttribute(iattn_mma3_kernel,
                         cudaFuncAttributeMaxDynamicSharedMemorySize, SMEM_TOTAL);
    iattn_mma3_kernel<<<grid, TPB, SMEM_TOTAL>>>(
        query, key_, value, bq, bk, bv, bo, out);
}